// round 4
// baseline (speedup 1.0000x reference)
#include <cuda_runtime.h>
#include <math.h>

#define L_TOK   4096
#define D_MODEL 1536
#define N_HEADS 12
#define H_DIM   128
#define QK_SCALE 0.08838834764831845f  /* 1/sqrt(128) */

// -------- scratch (allocation-free: __device__ globals) --------
__device__ float g_Q[L_TOK * D_MODEL];
__device__ float g_K[L_TOK * D_MODEL];
__device__ float g_V[L_TOK * D_MODEL];
__device__ float g_A[L_TOK * D_MODEL];

// =================================================================
// GEMM: C[M,N] = A[M,K] @ W[N,K]^T + bias   (all row-major fp32)
// 128x128 block tile, BK=16, 256 threads, 8x8 register micro-tile
// =================================================================
__global__ __launch_bounds__(256) void sgemm_bias_kernel(
    const float* __restrict__ A, const float* __restrict__ W,
    const float* __restrict__ bias, float* __restrict__ C,
    int M, int N, int K)
{
    __shared__ __align__(16) float As[16][132];
    __shared__ __align__(16) float Ws[16][132];
    const int tid = threadIdx.x;
    const int tx = tid & 15;
    const int ty = tid >> 4;
    const int bm = blockIdx.y * 128;
    const int bn = blockIdx.x * 128;

    const int lr = tid >> 2;        // 0..63
    const int lc = (tid & 3) * 4;   // 0,4,8,12

    float acc[8][8];
#pragma unroll
    for (int i = 0; i < 8; i++)
#pragma unroll
        for (int j = 0; j < 8; j++) acc[i][j] = 0.f;

    const float* Aptr0 = A + (size_t)(bm + lr) * K + lc;
    const float* Aptr1 = A + (size_t)(bm + lr + 64) * K + lc;
    const float* Wptr0 = W + (size_t)(bn + lr) * K + lc;
    const float* Wptr1 = W + (size_t)(bn + lr + 64) * K + lc;

    for (int k0 = 0; k0 < K; k0 += 16) {
        float4 a0 = *(const float4*)(Aptr0 + k0);
        float4 a1 = *(const float4*)(Aptr1 + k0);
        float4 w0 = *(const float4*)(Wptr0 + k0);
        float4 w1 = *(const float4*)(Wptr1 + k0);
        __syncthreads();
        As[lc+0][lr]    = a0.x; As[lc+1][lr]    = a0.y; As[lc+2][lr]    = a0.z; As[lc+3][lr]    = a0.w;
        As[lc+0][lr+64] = a1.x; As[lc+1][lr+64] = a1.y; As[lc+2][lr+64] = a1.z; As[lc+3][lr+64] = a1.w;
        Ws[lc+0][lr]    = w0.x; Ws[lc+1][lr]    = w0.y; Ws[lc+2][lr]    = w0.z; Ws[lc+3][lr]    = w0.w;
        Ws[lc+0][lr+64] = w1.x; Ws[lc+1][lr+64] = w1.y; Ws[lc+2][lr+64] = w1.z; Ws[lc+3][lr+64] = w1.w;
        __syncthreads();
#pragma unroll
        for (int kk = 0; kk < 16; kk++) {
            float av[8], wv[8];
            *(float4*)&av[0] = *(const float4*)&As[kk][ty*8];
            *(float4*)&av[4] = *(const float4*)&As[kk][ty*8+4];
            *(float4*)&wv[0] = *(const float4*)&Ws[kk][tx*8];
            *(float4*)&wv[4] = *(const float4*)&Ws[kk][tx*8+4];
#pragma unroll
            for (int i = 0; i < 8; i++)
#pragma unroll
                for (int j = 0; j < 8; j++)
                    acc[i][j] = fmaf(av[i], wv[j], acc[i][j]);
        }
    }

#pragma unroll
    for (int i = 0; i < 8; i++) {
        int row = bm + ty*8 + i;
#pragma unroll
        for (int j = 0; j < 8; j += 4) {
            int col = bn + tx*8 + j;
            float4 r;
            r.x = acc[i][j+0] + bias[col+0];
            r.y = acc[i][j+1] + bias[col+1];
            r.z = acc[i][j+2] + bias[col+2];
            r.w = acc[i][j+3] + bias[col+3];
            *(float4*)&C[(size_t)row * N + col] = r;
        }
    }
}

// =================================================================
// Fused full-D RMSNorm + 3-axis RoPE, in-place on g_Q / g_K.
// grid = (L_TOK, 2): y=0 -> Q with gq, y=1 -> K with gk. 256 thr.
// Band map (C=64): c<22 -> f-axis, 22<=c<43 -> h-axis, else w-axis.
// F=4, H=32, W=32 hardcoded (problem constants; l = f*1024+h*32+w).
// =================================================================
__global__ __launch_bounds__(256) void norm_rope_kernel(
    const float* __restrict__ gq, const float* __restrict__ gk,
    const float* __restrict__ fcos, const float* __restrict__ fsin)
{
    const int l = blockIdx.x;
    float* row = (blockIdx.y == 0 ? g_Q : g_K) + (size_t)l * D_MODEL;
    const float* g = (blockIdx.y == 0) ? gq : gk;
    const int tid = threadIdx.x;

    float2 v[3];
    float ss = 0.f;
#pragma unroll
    for (int t = 0; t < 3; t++) {
        int p = tid + t * 256;
        v[t] = *(const float2*)&row[2*p];
        ss += v[t].x*v[t].x + v[t].y*v[t].y;
    }
#pragma unroll
    for (int s = 16; s; s >>= 1) ss += __shfl_xor_sync(0xffffffffu, ss, s);

    __shared__ float warp_ss[8];
    __shared__ float inv_s;
    if ((tid & 31) == 0) warp_ss[tid >> 5] = ss;
    __syncthreads();
    if (tid == 0) {
        float tot = 0.f;
#pragma unroll
        for (int i = 0; i < 8; i++) tot += warp_ss[i];
        inv_s = rsqrtf(tot / (float)D_MODEL + 1e-6f);
    }
    __syncthreads();
    const float inv = inv_s;

    const int fi = l >> 10;
    const int hi = (l >> 5) & 31;
    const int wi = l & 31;

#pragma unroll
    for (int t = 0; t < 3; t++) {
        int p = tid + t * 256;       // pair index 0..767
        int c = p & 63;              // complex channel within head
        int rowi = (c < 22) ? fi : ((c < 43) ? hi : wi);
        float cv = fcos[rowi * 64 + c];
        float sv = fsin[rowi * 64 + c];
        float xr = v[t].x * inv * g[2*p];
        float xi = v[t].y * inv * g[2*p+1];
        float2 o;
        o.x = xr * cv - xi * sv;
        o.y = xr * sv + xi * cv;
        *(float2*)&row[2*p] = o;
    }
}

// =================================================================
// fp32 flash attention. grid = (L/64 qblocks, 12 heads), 256 thr.
// 64x64 score tiles, d=128. Q/K in XOR-swizzled smem (conflict-free
// transpose-free stores + 2-phase reads), V natural, P transposed.
// Online softmax per row with half-warp shuffle reductions.
// Dynamic smem = 3*64*128 + 64*68 floats = 115712 B.
// =================================================================
#define ATT_SMEM_BYTES ((3*64*128 + 64*68) * 4)

__global__ __launch_bounds__(256) void attn_kernel(
    const float* __restrict__ Q, const float* __restrict__ K,
    const float* __restrict__ V, float* __restrict__ O)
{
    extern __shared__ __align__(16) float sm[];
    float* Qs = sm;                  // [64][128] swizzled
    float* Ks = sm + 64*128;         // [64][128] swizzled
    float* Vs = sm + 2*64*128;       // [64][128] natural
    float* Ps = sm + 3*64*128;       // [64][68]  (Ps[j][i])

    const int tid  = threadIdx.x;
    const int tx   = tid & 15;
    const int ty   = tid >> 4;
    const int head = blockIdx.y;
    const int q0   = blockIdx.x * 64;
    const int hoff = head * H_DIM;

    // load Q tile, pre-scaled by 1/sqrt(d)
#pragma unroll
    for (int it = 0; it < 8; it++) {
        int ci = it*256 + tid;
        int i  = ci >> 5;
        int cq = ci & 31;
        float4 qv = *(const float4*)&Q[(size_t)(q0+i)*D_MODEL + hoff + cq*4];
        qv.x *= QK_SCALE; qv.y *= QK_SCALE; qv.z *= QK_SCALE; qv.w *= QK_SCALE;
        *(float4*)&Qs[i*128 + ((cq ^ ((i>>2)&7)) << 2)] = qv;
    }

    float m_i[4], l_i[4], Oacc[4][8];
#pragma unroll
    for (int ii = 0; ii < 4; ii++) {
        m_i[ii] = -1e30f; l_i[ii] = 0.f;
#pragma unroll
        for (int jj = 0; jj < 8; jj++) Oacc[ii][jj] = 0.f;
    }

    for (int kb = 0; kb < L_TOK/64; kb++) {
        const int k0 = kb * 64;
        __syncthreads();   // previous PV reads of Ks/Vs/Ps complete
#pragma unroll
        for (int it = 0; it < 8; it++) {
            int ci = it*256 + tid;
            int j  = ci >> 5;
            int cq = ci & 31;
            *(float4*)&Ks[j*128 + ((cq ^ ((j>>2)&7)) << 2)] =
                *(const float4*)&K[(size_t)(k0+j)*D_MODEL + hoff + cq*4];
            *(float4*)&Vs[j*128 + cq*4] =
                *(const float4*)&V[(size_t)(k0+j)*D_MODEL + hoff + cq*4];
        }
        __syncthreads();

        // ---- S = Qb @ Kb^T (pre-scaled) ----
        float s[4][4];
#pragma unroll
        for (int ii = 0; ii < 4; ii++)
#pragma unroll
            for (int jj = 0; jj < 4; jj++) s[ii][jj] = 0.f;

#pragma unroll
        for (int dq = 0; dq < 32; dq++) {
            float4 qa[4], kv[4];
            const int qo = (dq ^ (ty & 7)) << 2;
            const int ko = (dq ^ (tx & 7)) << 2;
#pragma unroll
            for (int ii = 0; ii < 4; ii++) qa[ii] = *(const float4*)&Qs[(ty*4+ii)*128 + qo];
#pragma unroll
            for (int jj = 0; jj < 4; jj++) kv[jj] = *(const float4*)&Ks[(tx*4+jj)*128 + ko];
#pragma unroll
            for (int ii = 0; ii < 4; ii++)
#pragma unroll
                for (int jj = 0; jj < 4; jj++) {
                    s[ii][jj] = fmaf(qa[ii].x, kv[jj].x, s[ii][jj]);
                    s[ii][jj] = fmaf(qa[ii].y, kv[jj].y, s[ii][jj]);
                    s[ii][jj] = fmaf(qa[ii].z, kv[jj].z, s[ii][jj]);
                    s[ii][jj] = fmaf(qa[ii].w, kv[jj].w, s[ii][jj]);
                }
        }

        // ---- online softmax (rows owned by 16-lane half-warp groups) ----
#pragma unroll
        for (int ii = 0; ii < 4; ii++) {
            float rm = fmaxf(fmaxf(s[ii][0], s[ii][1]), fmaxf(s[ii][2], s[ii][3]));
            rm = fmaxf(rm, __shfl_xor_sync(0xffffffffu, rm, 1));
            rm = fmaxf(rm, __shfl_xor_sync(0xffffffffu, rm, 2));
            rm = fmaxf(rm, __shfl_xor_sync(0xffffffffu, rm, 4));
            rm = fmaxf(rm, __shfl_xor_sync(0xffffffffu, rm, 8));
            float mnew = fmaxf(m_i[ii], rm);
            float corr = __expf(m_i[ii] - mnew);
            m_i[ii] = mnew;
            float rs = 0.f;
#pragma unroll
            for (int jj = 0; jj < 4; jj++) {
                float p = __expf(s[ii][jj] - mnew);
                s[ii][jj] = p;
                rs += p;
            }
            rs += __shfl_xor_sync(0xffffffffu, rs, 1);
            rs += __shfl_xor_sync(0xffffffffu, rs, 2);
            rs += __shfl_xor_sync(0xffffffffu, rs, 4);
            rs += __shfl_xor_sync(0xffffffffu, rs, 8);
            l_i[ii] = l_i[ii] * corr + rs;
#pragma unroll
            for (int jj = 0; jj < 8; jj++) Oacc[ii][jj] *= corr;
        }

        // store P transposed: Ps[j][i]
#pragma unroll
        for (int jj = 0; jj < 4; jj++)
#pragma unroll
            for (int ii = 0; ii < 4; ii++)
                Ps[(tx*4+jj)*68 + ty*4+ii] = s[ii][jj];
        __syncthreads();

        // ---- O += P @ Vb ----
#pragma unroll 8
        for (int j = 0; j < 64; j++) {
            float4 a  = *(const float4*)&Ps[j*68 + ty*4];
            float4 b0 = *(const float4*)&Vs[j*128 + tx*8];
            float4 b1 = *(const float4*)&Vs[j*128 + tx*8 + 4];
            float av[4] = {a.x, a.y, a.z, a.w};
#pragma unroll
            for (int ii = 0; ii < 4; ii++) {
                Oacc[ii][0] = fmaf(av[ii], b0.x, Oacc[ii][0]);
                Oacc[ii][1] = fmaf(av[ii], b0.y, Oacc[ii][1]);
                Oacc[ii][2] = fmaf(av[ii], b0.z, Oacc[ii][2]);
                Oacc[ii][3] = fmaf(av[ii], b0.w, Oacc[ii][3]);
                Oacc[ii][4] = fmaf(av[ii], b1.x, Oacc[ii][4]);
                Oacc[ii][5] = fmaf(av[ii], b1.y, Oacc[ii][5]);
                Oacc[ii][6] = fmaf(av[ii], b1.z, Oacc[ii][6]);
                Oacc[ii][7] = fmaf(av[ii], b1.w, Oacc[ii][7]);
            }
        }
    }

    // ---- epilogue: normalize and write ----
#pragma unroll
    for (int ii = 0; ii < 4; ii++) {
        float invl = 1.f / l_i[ii];
        int r = q0 + ty*4 + ii;
        float4 o0, o1;
        o0.x = Oacc[ii][0]*invl; o0.y = Oacc[ii][1]*invl;
        o0.z = Oacc[ii][2]*invl; o0.w = Oacc[ii][3]*invl;
        o1.x = Oacc[ii][4]*invl; o1.y = Oacc[ii][5]*invl;
        o1.z = Oacc[ii][6]*invl; o1.w = Oacc[ii][7]*invl;
        *(float4*)&O[(size_t)r*D_MODEL + hoff + tx*8]     = o0;
        *(float4*)&O[(size_t)r*D_MODEL + hoff + tx*8 + 4] = o1;
    }
}

// =================================================================
// launch
// =================================================================
extern "C" void kernel_launch(void* const* d_in, const int* in_sizes, int n_in,
                              void* d_out, int out_size)
{
    (void)in_sizes; (void)n_in; (void)out_size;
    const float* x    = (const float*)d_in[0];
    const float* wq   = (const float*)d_in[1];
    const float* wk   = (const float*)d_in[2];
    const float* wv   = (const float*)d_in[3];
    const float* wo   = (const float*)d_in[4];
    const float* bq   = (const float*)d_in[5];
    const float* bk   = (const float*)d_in[6];
    const float* bv   = (const float*)d_in[7];
    const float* bo   = (const float*)d_in[8];
    const float* gq   = (const float*)d_in[9];
    const float* gk   = (const float*)d_in[10];
    const float* fcos = (const float*)d_in[11];
    const float* fsin = (const float*)d_in[12];

    float *Qp, *Kp, *Vp, *Ap;
    cudaGetSymbolAddress((void**)&Qp, g_Q);
    cudaGetSymbolAddress((void**)&Kp, g_K);
    cudaGetSymbolAddress((void**)&Vp, g_V);
    cudaGetSymbolAddress((void**)&Ap, g_A);

    cudaFuncSetAttribute(attn_kernel, cudaFuncAttributeMaxDynamicSharedMemorySize,
                         ATT_SMEM_BYTES);

    dim3 gemm_grid(D_MODEL/128, L_TOK/128);   // (12, 32)

    sgemm_bias_kernel<<<gemm_grid, 256>>>(x, wq, bq, Qp, L_TOK, D_MODEL, D_MODEL);
    sgemm_bias_kernel<<<gemm_grid, 256>>>(x, wk, bk, Kp, L_TOK, D_MODEL, D_MODEL);
    sgemm_bias_kernel<<<gemm_grid, 256>>>(x, wv, bv, Vp, L_TOK, D_MODEL, D_MODEL);

    norm_rope_kernel<<<dim3(L_TOK, 2), 256>>>(gq, gk, fcos, fsin);

    attn_kernel<<<dim3(L_TOK/64, N_HEADS), 256, ATT_SMEM_BYTES>>>(Qp, Kp, Vp, Ap);

    sgemm_bias_kernel<<<gemm_grid, 256>>>(Ap, wo, bo, (float*)d_out,
                                          L_TOK, D_MODEL, D_MODEL);
}

// round 8
// speedup vs baseline: 1.2464x; 1.2464x over previous
#include <cuda_runtime.h>
#include <math.h>
#include <stdint.h>

#define L_TOK   4096
#define D_MODEL 1536
#define N_HEADS 12
#define H_DIM   128
#define QK_SCALE 0.08838834764831845f  /* 1/sqrt(128) */

// -------- scratch (allocation-free: __device__ globals) --------
__device__ float g_Q[L_TOK * D_MODEL];
__device__ float g_K[L_TOK * D_MODEL];
__device__ float g_V[L_TOK * D_MODEL];
__device__ float g_A[L_TOK * D_MODEL];

// =================================================================
// helpers
// =================================================================
__device__ __forceinline__ uint32_t tf32r(float x) {
    uint32_t r;
    asm("cvt.rna.tf32.f32 %0, %1;" : "=r"(r) : "f"(x));
    return r;
}

// D(m16n8) += A(m16k8,row) * B(k8n8,col)   tf32 inputs, f32 accum
__device__ __forceinline__ void mma_tf32(float* d,
                                         uint32_t a0, uint32_t a1,
                                         uint32_t a2, uint32_t a3,
                                         uint32_t b0, uint32_t b1) {
    asm volatile(
        "mma.sync.aligned.m16n8k8.row.col.f32.tf32.tf32.f32 "
        "{%0,%1,%2,%3}, {%4,%5,%6,%7}, {%8,%9}, {%0,%1,%2,%3};"
        : "+f"(d[0]), "+f"(d[1]), "+f"(d[2]), "+f"(d[3])
        : "r"(a0), "r"(a1), "r"(a2), "r"(a3), "r"(b0), "r"(b1));
}

// =================================================================
// tf32 mma.sync GEMM: C[M,N] = A[M,K] @ W[N,K]^T + bias (row-major f32)
// CTA 128x128, 8 warps (4 along M x 2 along N), warp tile 32x64.
// BK=32 staged in smem with stride-36 padding (conflict-free fragment
// reads: bank base = 4*row mod 32). tf32 conversion at smem store.
// =================================================================
#define SROW 36

__global__ __launch_bounds__(256) void mma_gemm_kernel(
    const float* __restrict__ A, const float* __restrict__ W,
    const float* __restrict__ bias, float* __restrict__ C,
    int M, int N, int K)
{
    __shared__ uint32_t As[128 * SROW];
    __shared__ uint32_t Ws[128 * SROW];

    const int tid    = threadIdx.x;
    const int wid    = tid >> 5;
    const int lane   = tid & 31;
    const int warp_m = wid & 3;       // 0..3  (M)
    const int warp_n = wid >> 2;      // 0..1  (N)
    const int bm     = blockIdx.y * 128;
    const int bn     = blockIdx.x * 128;
    const int g      = lane >> 2;     // 0..7
    const int q      = lane & 3;      // 0..3

    float acc[2][8][4];
#pragma unroll
    for (int mt = 0; mt < 2; mt++)
#pragma unroll
        for (int nt = 0; nt < 8; nt++)
#pragma unroll
            for (int c = 0; c < 4; c++) acc[mt][nt][c] = 0.f;

    // loader mapping: 2 threads per row, each covers 16 consecutive k
    const int lrow  = tid >> 1;              // 0..127
    const int lhalf = (tid & 1) * 16;        // 0 or 16
    const float* Ap = A + (size_t)(bm + lrow) * K + lhalf;
    const float* Wp = W + (size_t)(bn + lrow) * K + lhalf;
    const uint32_t sOff = (uint32_t)lrow * SROW + (uint32_t)lhalf;

    float4 pa[4], pw[4];
#pragma unroll
    for (int i = 0; i < 4; i++) {
        pa[i] = *(const float4*)(Ap + i * 4);
        pw[i] = *(const float4*)(Wp + i * 4);
    }

    const int aBaseM0 = warp_m * 32;
    const int bBaseN  = warp_n * 64;

    for (int k0 = 0; k0 < K; k0 += 32) {
        __syncthreads();   // previous iteration's fragment reads done
#pragma unroll
        for (int i = 0; i < 4; i++) {
            uint4 va = make_uint4(tf32r(pa[i].x), tf32r(pa[i].y),
                                  tf32r(pa[i].z), tf32r(pa[i].w));
            uint4 vw = make_uint4(tf32r(pw[i].x), tf32r(pw[i].y),
                                  tf32r(pw[i].z), tf32r(pw[i].w));
            *(uint4*)&As[sOff + i * 4] = va;
            *(uint4*)&Ws[sOff + i * 4] = vw;
        }
        __syncthreads();

        if (k0 + 32 < K) {
            const float* Ap2 = Ap + k0 + 32;
            const float* Wp2 = Wp + k0 + 32;
#pragma unroll
            for (int i = 0; i < 4; i++) {
                pa[i] = *(const float4*)(Ap2 + i * 4);
                pw[i] = *(const float4*)(Wp2 + i * 4);
            }
        }

#pragma unroll
        for (int ks = 0; ks < 4; ks++) {
            const int kk = ks * 8;
            uint32_t a[2][4];
#pragma unroll
            for (int mt = 0; mt < 2; mt++) {
                const int r = aBaseM0 + mt * 16;
                a[mt][0] = As[(r + g)     * SROW + kk + q];
                a[mt][1] = As[(r + g + 8) * SROW + kk + q];
                a[mt][2] = As[(r + g)     * SROW + kk + q + 4];
                a[mt][3] = As[(r + g + 8) * SROW + kk + q + 4];
            }
#pragma unroll
            for (int nt = 0; nt < 8; nt++) {
                const int c = bBaseN + nt * 8;
                uint32_t b0 = Ws[(c + g) * SROW + kk + q];
                uint32_t b1 = Ws[(c + g) * SROW + kk + q + 4];
                mma_tf32(acc[0][nt], a[0][0], a[0][1], a[0][2], a[0][3], b0, b1);
                mma_tf32(acc[1][nt], a[1][0], a[1][1], a[1][2], a[1][3], b0, b1);
            }
        }
    }

    // epilogue: D fragment c0,c1 -> (row g, col 2q/2q+1); c2,c3 -> row g+8
#pragma unroll
    for (int mt = 0; mt < 2; mt++) {
        const int row0 = bm + aBaseM0 + mt * 16 + g;
#pragma unroll
        for (int nt = 0; nt < 8; nt++) {
            const int col = bn + bBaseN + nt * 8 + q * 2;
            const float2 bb = *(const float2*)&bias[col];
            float2 r0, r1;
            r0.x = acc[mt][nt][0] + bb.x;
            r0.y = acc[mt][nt][1] + bb.y;
            r1.x = acc[mt][nt][2] + bb.x;
            r1.y = acc[mt][nt][3] + bb.y;
            *(float2*)&C[(size_t)row0 * N + col]       = r0;
            *(float2*)&C[(size_t)(row0 + 8) * N + col] = r1;
        }
    }
}

// =================================================================
// Fused full-D RMSNorm + 3-axis RoPE, in-place on g_Q / g_K.
// =================================================================
__global__ __launch_bounds__(256) void norm_rope_kernel(
    const float* __restrict__ gq, const float* __restrict__ gk,
    const float* __restrict__ fcos, const float* __restrict__ fsin)
{
    const int l = blockIdx.x;
    float* row = (blockIdx.y == 0 ? g_Q : g_K) + (size_t)l * D_MODEL;
    const float* g = (blockIdx.y == 0) ? gq : gk;
    const int tid = threadIdx.x;

    float2 v[3];
    float ss = 0.f;
#pragma unroll
    for (int t = 0; t < 3; t++) {
        int p = tid + t * 256;
        v[t] = *(const float2*)&row[2*p];
        ss += v[t].x*v[t].x + v[t].y*v[t].y;
    }
#pragma unroll
    for (int s = 16; s; s >>= 1) ss += __shfl_xor_sync(0xffffffffu, ss, s);

    __shared__ float warp_ss[8];
    __shared__ float inv_s;
    if ((tid & 31) == 0) warp_ss[tid >> 5] = ss;
    __syncthreads();
    if (tid == 0) {
        float tot = 0.f;
#pragma unroll
        for (int i = 0; i < 8; i++) tot += warp_ss[i];
        inv_s = rsqrtf(tot / (float)D_MODEL + 1e-6f);
    }
    __syncthreads();
    const float inv = inv_s;

    const int fi = l >> 10;
    const int hi = (l >> 5) & 31;
    const int wi = l & 31;

#pragma unroll
    for (int t = 0; t < 3; t++) {
        int p = tid + t * 256;
        int c = p & 63;
        int rowi = (c < 22) ? fi : ((c < 43) ? hi : wi);
        float cv = fcos[rowi * 64 + c];
        float sv = fsin[rowi * 64 + c];
        float xr = v[t].x * inv * g[2*p];
        float xi = v[t].y * inv * g[2*p+1];
        float2 o;
        o.x = xr * cv - xi * sv;
        o.y = xr * sv + xi * cv;
        *(float2*)&row[2*p] = o;
    }
}

// =================================================================
// fp32 flash attention (unchanged from passing R1 kernel)
// =================================================================
#define ATT_SMEM_BYTES ((3*64*128 + 64*68) * 4)

__global__ __launch_bounds__(256) void attn_kernel(
    const float* __restrict__ Q, const float* __restrict__ K,
    const float* __restrict__ V, float* __restrict__ O)
{
    extern __shared__ __align__(16) float sm[];
    float* Qs = sm;
    float* Ks = sm + 64*128;
    float* Vs = sm + 2*64*128;
    float* Ps = sm + 3*64*128;

    const int tid  = threadIdx.x;
    const int tx   = tid & 15;
    const int ty   = tid >> 4;
    const int head = blockIdx.y;
    const int q0   = blockIdx.x * 64;
    const int hoff = head * H_DIM;

#pragma unroll
    for (int it = 0; it < 8; it++) {
        int ci = it*256 + tid;
        int i  = ci >> 5;
        int cq = ci & 31;
        float4 qv = *(const float4*)&Q[(size_t)(q0+i)*D_MODEL + hoff + cq*4];
        qv.x *= QK_SCALE; qv.y *= QK_SCALE; qv.z *= QK_SCALE; qv.w *= QK_SCALE;
        *(float4*)&Qs[i*128 + ((cq ^ ((i>>2)&7)) << 2)] = qv;
    }

    float m_i[4], l_i[4], Oacc[4][8];
#pragma unroll
    for (int ii = 0; ii < 4; ii++) {
        m_i[ii] = -1e30f; l_i[ii] = 0.f;
#pragma unroll
        for (int jj = 0; jj < 8; jj++) Oacc[ii][jj] = 0.f;
    }

    for (int kb = 0; kb < L_TOK/64; kb++) {
        const int k0 = kb * 64;
        __syncthreads();
#pragma unroll
        for (int it = 0; it < 8; it++) {
            int ci = it*256 + tid;
            int j  = ci >> 5;
            int cq = ci & 31;
            *(float4*)&Ks[j*128 + ((cq ^ ((j>>2)&7)) << 2)] =
                *(const float4*)&K[(size_t)(k0+j)*D_MODEL + hoff + cq*4];
            *(float4*)&Vs[j*128 + cq*4] =
                *(const float4*)&V[(size_t)(k0+j)*D_MODEL + hoff + cq*4];
        }
        __syncthreads();

        float s[4][4];
#pragma unroll
        for (int ii = 0; ii < 4; ii++)
#pragma unroll
            for (int jj = 0; jj < 4; jj++) s[ii][jj] = 0.f;

#pragma unroll
        for (int dq = 0; dq < 32; dq++) {
            float4 qa[4], kv[4];
            const int qo = (dq ^ (ty & 7)) << 2;
            const int ko = (dq ^ (tx & 7)) << 2;
#pragma unroll
            for (int ii = 0; ii < 4; ii++) qa[ii] = *(const float4*)&Qs[(ty*4+ii)*128 + qo];
#pragma unroll
            for (int jj = 0; jj < 4; jj++) kv[jj] = *(const float4*)&Ks[(tx*4+jj)*128 + ko];
#pragma unroll
            for (int ii = 0; ii < 4; ii++)
#pragma unroll
                for (int jj = 0; jj < 4; jj++) {
                    s[ii][jj] = fmaf(qa[ii].x, kv[jj].x, s[ii][jj]);
                    s[ii][jj] = fmaf(qa[ii].y, kv[jj].y, s[ii][jj]);
                    s[ii][jj] = fmaf(qa[ii].z, kv[jj].z, s[ii][jj]);
                    s[ii][jj] = fmaf(qa[ii].w, kv[jj].w, s[ii][jj]);
                }
        }

#pragma unroll
        for (int ii = 0; ii < 4; ii++) {
            float rm = fmaxf(fmaxf(s[ii][0], s[ii][1]), fmaxf(s[ii][2], s[ii][3]));
            rm = fmaxf(rm, __shfl_xor_sync(0xffffffffu, rm, 1));
            rm = fmaxf(rm, __shfl_xor_sync(0xffffffffu, rm, 2));
            rm = fmaxf(rm, __shfl_xor_sync(0xffffffffu, rm, 4));
            rm = fmaxf(rm, __shfl_xor_sync(0xffffffffu, rm, 8));
            float mnew = fmaxf(m_i[ii], rm);
            float corr = __expf(m_i[ii] - mnew);
            m_i[ii] = mnew;
            float rs = 0.f;
#pragma unroll
            for (int jj = 0; jj < 4; jj++) {
                float p = __expf(s[ii][jj] - mnew);
                s[ii][jj] = p;
                rs += p;
            }
            rs += __shfl_xor_sync(0xffffffffu, rs, 1);
            rs += __shfl_xor_sync(0xffffffffu, rs, 2);
            rs += __shfl_xor_sync(0xffffffffu, rs, 4);
            rs += __shfl_xor_sync(0xffffffffu, rs, 8);
            l_i[ii] = l_i[ii] * corr + rs;
#pragma unroll
            for (int jj = 0; jj < 8; jj++) Oacc[ii][jj] *= corr;
        }

#pragma unroll
        for (int jj = 0; jj < 4; jj++)
#pragma unroll
            for (int ii = 0; ii < 4; ii++)
                Ps[(tx*4+jj)*68 + ty*4+ii] = s[ii][jj];
        __syncthreads();

#pragma unroll 8
        for (int j = 0; j < 64; j++) {
            float4 a  = *(const float4*)&Ps[j*68 + ty*4];
            float4 b0 = *(const float4*)&Vs[j*128 + tx*8];
            float4 b1 = *(const float4*)&Vs[j*128 + tx*8 + 4];
            float av2[4] = {a.x, a.y, a.z, a.w};
#pragma unroll
            for (int ii = 0; ii < 4; ii++) {
                Oacc[ii][0] = fmaf(av2[ii], b0.x, Oacc[ii][0]);
                Oacc[ii][1] = fmaf(av2[ii], b0.y, Oacc[ii][1]);
                Oacc[ii][2] = fmaf(av2[ii], b0.z, Oacc[ii][2]);
                Oacc[ii][3] = fmaf(av2[ii], b0.w, Oacc[ii][3]);
                Oacc[ii][4] = fmaf(av2[ii], b1.x, Oacc[ii][4]);
                Oacc[ii][5] = fmaf(av2[ii], b1.y, Oacc[ii][5]);
                Oacc[ii][6] = fmaf(av2[ii], b1.z, Oacc[ii][6]);
                Oacc[ii][7] = fmaf(av2[ii], b1.w, Oacc[ii][7]);
            }
        }
    }

#pragma unroll
    for (int ii = 0; ii < 4; ii++) {
        float invl = 1.f / l_i[ii];
        int r = q0 + ty*4 + ii;
        float4 o0, o1;
        o0.x = Oacc[ii][0]*invl; o0.y = Oacc[ii][1]*invl;
        o0.z = Oacc[ii][2]*invl; o0.w = Oacc[ii][3]*invl;
        o1.x = Oacc[ii][4]*invl; o1.y = Oacc[ii][5]*invl;
        o1.z = Oacc[ii][6]*invl; o1.w = Oacc[ii][7]*invl;
        *(float4*)&O[(size_t)r*D_MODEL + hoff + tx*8]     = o0;
        *(float4*)&O[(size_t)r*D_MODEL + hoff + tx*8 + 4] = o1;
    }
}

// =================================================================
// launch
// =================================================================
extern "C" void kernel_launch(void* const* d_in, const int* in_sizes, int n_in,
                              void* d_out, int out_size)
{
    (void)in_sizes; (void)n_in; (void)out_size;
    const float* x    = (const float*)d_in[0];
    const float* wq   = (const float*)d_in[1];
    const float* wk   = (const float*)d_in[2];
    const float* wv   = (const float*)d_in[3];
    const float* wo   = (const float*)d_in[4];
    const float* bq   = (const float*)d_in[5];
    const float* bk   = (const float*)d_in[6];
    const float* bv   = (const float*)d_in[7];
    const float* bo   = (const float*)d_in[8];
    const float* gq   = (const float*)d_in[9];
    const float* gk   = (const float*)d_in[10];
    const float* fcos = (const float*)d_in[11];
    const float* fsin = (const float*)d_in[12];

    float *Qp, *Kp, *Vp, *Ap;
    cudaGetSymbolAddress((void**)&Qp, g_Q);
    cudaGetSymbolAddress((void**)&Kp, g_K);
    cudaGetSymbolAddress((void**)&Vp, g_V);
    cudaGetSymbolAddress((void**)&Ap, g_A);

    cudaFuncSetAttribute(attn_kernel, cudaFuncAttributeMaxDynamicSharedMemorySize,
                         ATT_SMEM_BYTES);

    dim3 gemm_grid(D_MODEL/128, L_TOK/128);   // (12, 32)

    mma_gemm_kernel<<<gemm_grid, 256>>>(x, wq, bq, Qp, L_TOK, D_MODEL, D_MODEL);
    mma_gemm_kernel<<<gemm_grid, 256>>>(x, wk, bk, Kp, L_TOK, D_MODEL, D_MODEL);
    mma_gemm_kernel<<<gemm_grid, 256>>>(x, wv, bv, Vp, L_TOK, D_MODEL, D_MODEL);

    norm_rope_kernel<<<dim3(L_TOK, 2), 256>>>(gq, gk, fcos, fsin);

    attn_kernel<<<dim3(L_TOK/64, N_HEADS), 256, ATT_SMEM_BYTES>>>(Qp, Kp, Vp, Ap);

    mma_gemm_kernel<<<gemm_grid, 256>>>(Ap, wo, bo, (float*)d_out,
                                        L_TOK, D_MODEL, D_MODEL);
}

// round 10
// speedup vs baseline: 3.1499x; 2.5273x over previous
#include <cuda_runtime.h>
#include <math.h>
#include <stdint.h>

#define L_TOK   4096
#define D_MODEL 1536
#define N_HEADS 12
#define H_DIM   128
#define QK_SCALE 0.08838834764831845f  /* 1/sqrt(128) */

// -------- scratch (allocation-free: __device__ globals) --------
__device__ float g_Q[L_TOK * D_MODEL];
__device__ float g_K[L_TOK * D_MODEL];
__device__ float g_V[L_TOK * D_MODEL];   // holds V^T: [D_MODEL][L_TOK]
__device__ float g_A[L_TOK * D_MODEL];

// =================================================================
// helpers
// =================================================================
__device__ __forceinline__ uint32_t tf32r(float x) {
    uint32_t r;
    asm("cvt.rna.tf32.f32 %0, %1;" : "=r"(r) : "f"(x));
    return r;
}

// D(m16n8) += A(m16k8,row) * B(k8n8,col)   tf32 inputs, f32 accum
__device__ __forceinline__ void mma_tf32(float* d,
                                         uint32_t a0, uint32_t a1,
                                         uint32_t a2, uint32_t a3,
                                         uint32_t b0, uint32_t b1) {
    asm volatile(
        "mma.sync.aligned.m16n8k8.row.col.f32.tf32.tf32.f32 "
        "{%0,%1,%2,%3}, {%4,%5,%6,%7}, {%8,%9}, {%0,%1,%2,%3};"
        : "+f"(d[0]), "+f"(d[1]), "+f"(d[2]), "+f"(d[3])
        : "r"(a0), "r"(a1), "r"(a2), "r"(a3), "r"(b0), "r"(b1));
}

// =================================================================
// tf32 mma.sync GEMM: C[M,N] = A[M,K] @ W[N,K]^T + bias (row-major)
// CTA 128x128, 8 warps (4 M x 2 N), warp tile 32x64, BK=32.
// TRANSPOSED=0: C row-major [M][N]; TRANSPOSED=1: C = C^T [N][M].
// =================================================================
#define SROW 36

template <int TRANSPOSED>
__global__ __launch_bounds__(256) void mma_gemm_kernel(
    const float* __restrict__ A, const float* __restrict__ W,
    const float* __restrict__ bias, float* __restrict__ C,
    int M, int N, int K)
{
    __shared__ uint32_t As[128 * SROW];
    __shared__ uint32_t Ws[128 * SROW];

    const int tid    = threadIdx.x;
    const int wid    = tid >> 5;
    const int lane   = tid & 31;
    const int warp_m = wid & 3;
    const int warp_n = wid >> 2;
    const int bm     = blockIdx.y * 128;
    const int bn     = blockIdx.x * 128;
    const int g      = lane >> 2;
    const int q      = lane & 3;

    float acc[2][8][4];
#pragma unroll
    for (int mt = 0; mt < 2; mt++)
#pragma unroll
        for (int nt = 0; nt < 8; nt++)
#pragma unroll
            for (int c = 0; c < 4; c++) acc[mt][nt][c] = 0.f;

    const int lrow  = tid >> 1;
    const int lhalf = (tid & 1) * 16;
    const float* Ap = A + (size_t)(bm + lrow) * K + lhalf;
    const float* Wp = W + (size_t)(bn + lrow) * K + lhalf;
    const uint32_t sOff = (uint32_t)lrow * SROW + (uint32_t)lhalf;

    float4 pa[4], pw[4];
#pragma unroll
    for (int i = 0; i < 4; i++) {
        pa[i] = *(const float4*)(Ap + i * 4);
        pw[i] = *(const float4*)(Wp + i * 4);
    }

    const int aBaseM0 = warp_m * 32;
    const int bBaseN  = warp_n * 64;

    for (int k0 = 0; k0 < K; k0 += 32) {
        __syncthreads();
#pragma unroll
        for (int i = 0; i < 4; i++) {
            uint4 va = make_uint4(tf32r(pa[i].x), tf32r(pa[i].y),
                                  tf32r(pa[i].z), tf32r(pa[i].w));
            uint4 vw = make_uint4(tf32r(pw[i].x), tf32r(pw[i].y),
                                  tf32r(pw[i].z), tf32r(pw[i].w));
            *(uint4*)&As[sOff + i * 4] = va;
            *(uint4*)&Ws[sOff + i * 4] = vw;
        }
        __syncthreads();

        if (k0 + 32 < K) {
            const float* Ap2 = Ap + k0 + 32;
            const float* Wp2 = Wp + k0 + 32;
#pragma unroll
            for (int i = 0; i < 4; i++) {
                pa[i] = *(const float4*)(Ap2 + i * 4);
                pw[i] = *(const float4*)(Wp2 + i * 4);
            }
        }

#pragma unroll
        for (int ks = 0; ks < 4; ks++) {
            const int kk = ks * 8;
            uint32_t a[2][4];
#pragma unroll
            for (int mt = 0; mt < 2; mt++) {
                const int r = aBaseM0 + mt * 16;
                a[mt][0] = As[(r + g)     * SROW + kk + q];
                a[mt][1] = As[(r + g + 8) * SROW + kk + q];
                a[mt][2] = As[(r + g)     * SROW + kk + q + 4];
                a[mt][3] = As[(r + g + 8) * SROW + kk + q + 4];
            }
#pragma unroll
            for (int nt = 0; nt < 8; nt++) {
                const int c = bBaseN + nt * 8;
                uint32_t b0 = Ws[(c + g) * SROW + kk + q];
                uint32_t b1 = Ws[(c + g) * SROW + kk + q + 4];
                mma_tf32(acc[0][nt], a[0][0], a[0][1], a[0][2], a[0][3], b0, b1);
                mma_tf32(acc[1][nt], a[1][0], a[1][1], a[1][2], a[1][3], b0, b1);
            }
        }
    }

#pragma unroll
    for (int mt = 0; mt < 2; mt++) {
        const int row0 = bm + aBaseM0 + mt * 16 + g;
#pragma unroll
        for (int nt = 0; nt < 8; nt++) {
            const int col = bn + bBaseN + nt * 8 + q * 2;
            const float2 bb = *(const float2*)&bias[col];
            if (TRANSPOSED) {
                // C^T[N][M]: element (row,col) stored at C[col*M + row]
                C[(size_t)col       * M + row0]     = acc[mt][nt][0] + bb.x;
                C[(size_t)(col + 1) * M + row0]     = acc[mt][nt][1] + bb.y;
                C[(size_t)col       * M + row0 + 8] = acc[mt][nt][2] + bb.x;
                C[(size_t)(col + 1) * M + row0 + 8] = acc[mt][nt][3] + bb.y;
            } else {
                float2 r0, r1;
                r0.x = acc[mt][nt][0] + bb.x;
                r0.y = acc[mt][nt][1] + bb.y;
                r1.x = acc[mt][nt][2] + bb.x;
                r1.y = acc[mt][nt][3] + bb.y;
                *(float2*)&C[(size_t)row0 * N + col]       = r0;
                *(float2*)&C[(size_t)(row0 + 8) * N + col] = r1;
            }
        }
    }
}

// =================================================================
// Fused full-D RMSNorm + 3-axis RoPE, in-place on g_Q / g_K.
// =================================================================
__global__ __launch_bounds__(256) void norm_rope_kernel(
    const float* __restrict__ gq, const float* __restrict__ gk,
    const float* __restrict__ fcos, const float* __restrict__ fsin)
{
    const int l = blockIdx.x;
    float* row = (blockIdx.y == 0 ? g_Q : g_K) + (size_t)l * D_MODEL;
    const float* g = (blockIdx.y == 0) ? gq : gk;
    const int tid = threadIdx.x;

    float2 v[3];
    float ss = 0.f;
#pragma unroll
    for (int t = 0; t < 3; t++) {
        int p = tid + t * 256;
        v[t] = *(const float2*)&row[2*p];
        ss += v[t].x*v[t].x + v[t].y*v[t].y;
    }
#pragma unroll
    for (int s = 16; s; s >>= 1) ss += __shfl_xor_sync(0xffffffffu, ss, s);

    __shared__ float warp_ss[8];
    __shared__ float inv_s;
    if ((tid & 31) == 0) warp_ss[tid >> 5] = ss;
    __syncthreads();
    if (tid == 0) {
        float tot = 0.f;
#pragma unroll
        for (int i = 0; i < 8; i++) tot += warp_ss[i];
        inv_s = rsqrtf(tot / (float)D_MODEL + 1e-6f);
    }
    __syncthreads();
    const float inv = inv_s;

    const int fi = l >> 10;
    const int hi = (l >> 5) & 31;
    const int wi = l & 31;

#pragma unroll
    for (int t = 0; t < 3; t++) {
        int p = tid + t * 256;
        int c = p & 63;
        int rowi = (c < 22) ? fi : ((c < 43) ? hi : wi);
        float cv = fcos[rowi * 64 + c];
        float sv = fsin[rowi * 64 + c];
        float xr = v[t].x * inv * g[2*p];
        float xi = v[t].y * inv * g[2*p+1];
        float2 o;
        o.x = xr * cv - xi * sv;
        o.y = xr * sv + xi * cv;
        *(float2*)&row[2*p] = o;
    }
}

// =================================================================
// tf32 mma.sync flash attention.
// CTA = 128 Q-rows x 1 head, 8 warps (16 rows each), K-tile = 64.
// Q fragments register-resident. K staged [tok][132]; V^T staged
// [d][68]; P via per-warp-private smem [row][68].
// grid (32, 12), 256 threads.
// smem words: Ks 64*132=8448 | Vts 128*68=8704 | Ps 128*68=8704
//   (Q staging reuses first 128*132=16896 words before the loop)
// =================================================================
#define AKS_OFF 0
#define AVT_OFF (64*132)
#define APS_OFF (64*132 + 128*68)
#define ATT_SMEM_WORDS (64*132 + 2*128*68)
#define ATT_SMEM_BYTES (ATT_SMEM_WORDS * 4)

__global__ __launch_bounds__(256) void attn_mma_kernel(
    const float* __restrict__ Q, const float* __restrict__ K,
    const float* __restrict__ Vt, float* __restrict__ O)
{
    extern __shared__ __align__(16) uint32_t smw[];
    const int tid  = threadIdx.x;
    const int lane = tid & 31;
    const int wid  = tid >> 5;
    const int g    = lane >> 2;
    const int q    = lane & 3;
    const int head = blockIdx.y;
    const int q0   = blockIdx.x * 128;
    const int hoff = head * H_DIM;
    const int mrow = wid * 16;

    // ---- stage Q (pre-scaled, tf32) then lift fragments to regs ----
#pragma unroll
    for (int it = 0; it < 16; it++) {
        int ci = it * 256 + tid;
        int r  = ci >> 5, cq = ci & 31;
        float4 v = *(const float4*)&Q[(size_t)(q0 + r) * D_MODEL + hoff + cq * 4];
        uint4 u = make_uint4(tf32r(v.x * QK_SCALE), tf32r(v.y * QK_SCALE),
                             tf32r(v.z * QK_SCALE), tf32r(v.w * QK_SCALE));
        *(uint4*)&smw[r * 132 + cq * 4] = u;
    }
    __syncthreads();
    uint32_t qa[16][4];
#pragma unroll
    for (int ks = 0; ks < 16; ks++) {
        const int kk = ks * 8;
        qa[ks][0] = smw[(mrow + g)     * 132 + kk + q];
        qa[ks][1] = smw[(mrow + g + 8) * 132 + kk + q];
        qa[ks][2] = smw[(mrow + g)     * 132 + kk + q + 4];
        qa[ks][3] = smw[(mrow + g + 8) * 132 + kk + q + 4];
    }

    uint32_t* Ks  = smw + AKS_OFF;
    uint32_t* Vts = smw + AVT_OFF;
    uint32_t* Ps  = smw + APS_OFF;

    float m0 = -1e30f, m1 = -1e30f, l0 = 0.f, l1 = 0.f;
    float Oa[16][4];
#pragma unroll
    for (int nt = 0; nt < 16; nt++)
#pragma unroll
        for (int c = 0; c < 4; c++) Oa[nt][c] = 0.f;

    for (int kb = 0; kb < L_TOK / 64; kb++) {
        const int k0 = kb * 64;
        __syncthreads();   // prior PV reads of Ks/Vts done (also covers Q stage)
        // stage K tile: 64 rows x 32 float4 (warp-per-row: conflict-free)
#pragma unroll
        for (int it = 0; it < 8; it++) {
            int ci = it * 256 + tid;
            int r  = ci >> 5, cq = ci & 31;
            float4 v = *(const float4*)&K[(size_t)(k0 + r) * D_MODEL + hoff + cq * 4];
            *(uint4*)&Ks[r * 132 + cq * 4] =
                make_uint4(tf32r(v.x), tf32r(v.y), tf32r(v.z), tf32r(v.w));
        }
        // stage V^T tile: 128 d-rows x 16 float4
#pragma unroll
        for (int it = 0; it < 8; it++) {
            int ci = it * 256 + tid;
            int r  = ci >> 4, cf = ci & 15;
            float4 v = *(const float4*)&Vt[(size_t)(hoff + r) * L_TOK + k0 + cf * 4];
            *(uint4*)&Vts[r * 68 + cf * 4] =
                make_uint4(tf32r(v.x), tf32r(v.y), tf32r(v.z), tf32r(v.w));
        }
        __syncthreads();

        // ---- S = Q K^T : 16 ksteps x 8 ntiles ----
        float s[8][4];
#pragma unroll
        for (int nt = 0; nt < 8; nt++)
#pragma unroll
            for (int c = 0; c < 4; c++) s[nt][c] = 0.f;

#pragma unroll
        for (int ks = 0; ks < 16; ks++) {
            const int kk = ks * 8;
#pragma unroll
            for (int nt = 0; nt < 8; nt++) {
                uint32_t b0 = Ks[(nt * 8 + g) * 132 + kk + q];
                uint32_t b1 = Ks[(nt * 8 + g) * 132 + kk + q + 4];
                mma_tf32(s[nt], qa[ks][0], qa[ks][1], qa[ks][2], qa[ks][3], b0, b1);
            }
        }

        // ---- online softmax (rows g -> c0,c1 ; g+8 -> c2,c3) ----
        float rm0 = -1e30f, rm1 = -1e30f;
#pragma unroll
        for (int nt = 0; nt < 8; nt++) {
            rm0 = fmaxf(rm0, fmaxf(s[nt][0], s[nt][1]));
            rm1 = fmaxf(rm1, fmaxf(s[nt][2], s[nt][3]));
        }
        rm0 = fmaxf(rm0, __shfl_xor_sync(0xffffffffu, rm0, 1));
        rm0 = fmaxf(rm0, __shfl_xor_sync(0xffffffffu, rm0, 2));
        rm1 = fmaxf(rm1, __shfl_xor_sync(0xffffffffu, rm1, 1));
        rm1 = fmaxf(rm1, __shfl_xor_sync(0xffffffffu, rm1, 2));

        const float mn0 = fmaxf(m0, rm0);
        const float mn1 = fmaxf(m1, rm1);
        const float cr0 = __expf(m0 - mn0);
        const float cr1 = __expf(m1 - mn1);
        m0 = mn0; m1 = mn1;

        float rs0 = 0.f, rs1 = 0.f;
#pragma unroll
        for (int nt = 0; nt < 8; nt++) {
            s[nt][0] = __expf(s[nt][0] - mn0);
            s[nt][1] = __expf(s[nt][1] - mn0);
            s[nt][2] = __expf(s[nt][2] - mn1);
            s[nt][3] = __expf(s[nt][3] - mn1);
            rs0 += s[nt][0] + s[nt][1];
            rs1 += s[nt][2] + s[nt][3];
        }
        rs0 += __shfl_xor_sync(0xffffffffu, rs0, 1);
        rs0 += __shfl_xor_sync(0xffffffffu, rs0, 2);
        rs1 += __shfl_xor_sync(0xffffffffu, rs1, 1);
        rs1 += __shfl_xor_sync(0xffffffffu, rs1, 2);
        l0 = l0 * cr0 + rs0;
        l1 = l1 * cr1 + rs1;

#pragma unroll
        for (int nt = 0; nt < 16; nt++) {
            Oa[nt][0] *= cr0; Oa[nt][1] *= cr0;
            Oa[nt][2] *= cr1; Oa[nt][3] *= cr1;
        }

        // P -> smem (tf32), per-warp-private rows
#pragma unroll
        for (int nt = 0; nt < 8; nt++) {
            *(uint2*)&Ps[(mrow + g)     * 68 + nt * 8 + 2 * q] =
                make_uint2(tf32r(s[nt][0]), tf32r(s[nt][1]));
            *(uint2*)&Ps[(mrow + g + 8) * 68 + nt * 8 + 2 * q] =
                make_uint2(tf32r(s[nt][2]), tf32r(s[nt][3]));
        }
        __syncwarp();

        // ---- O += P V : 8 ksteps x 16 ntiles ----
#pragma unroll
        for (int ks = 0; ks < 8; ks++) {
            const int kk = ks * 8;
            uint32_t pa0 = Ps[(mrow + g)     * 68 + kk + q];
            uint32_t pa1 = Ps[(mrow + g + 8) * 68 + kk + q];
            uint32_t pa2 = Ps[(mrow + g)     * 68 + kk + q + 4];
            uint32_t pa3 = Ps[(mrow + g + 8) * 68 + kk + q + 4];
#pragma unroll
            for (int nt = 0; nt < 16; nt++) {
                uint32_t b0 = Vts[(nt * 8 + g) * 68 + kk + q];
                uint32_t b1 = Vts[(nt * 8 + g) * 68 + kk + q + 4];
                mma_tf32(Oa[nt], pa0, pa1, pa2, pa3, b0, b1);
            }
        }
        __syncwarp();   // P reads done before next iter's P writes
    }

    // ---- epilogue ----
    const float i0 = 1.f / l0;
    const float i1 = 1.f / l1;
    const int r0 = q0 + mrow + g;
#pragma unroll
    for (int nt = 0; nt < 16; nt++) {
        const int col = hoff + nt * 8 + 2 * q;
        float2 w0, w1;
        w0.x = Oa[nt][0] * i0; w0.y = Oa[nt][1] * i0;
        w1.x = Oa[nt][2] * i1; w1.y = Oa[nt][3] * i1;
        *(float2*)&O[(size_t)r0 * D_MODEL + col]       = w0;
        *(float2*)&O[(size_t)(r0 + 8) * D_MODEL + col] = w1;
    }
}

// =================================================================
// launch
// =================================================================
extern "C" void kernel_launch(void* const* d_in, const int* in_sizes, int n_in,
                              void* d_out, int out_size)
{
    (void)in_sizes; (void)n_in; (void)out_size;
    const float* x    = (const float*)d_in[0];
    const float* wq   = (const float*)d_in[1];
    const float* wk   = (const float*)d_in[2];
    const float* wv   = (const float*)d_in[3];
    const float* wo   = (const float*)d_in[4];
    const float* bq   = (const float*)d_in[5];
    const float* bk   = (const float*)d_in[6];
    const float* bv   = (const float*)d_in[7];
    const float* bo   = (const float*)d_in[8];
    const float* gq   = (const float*)d_in[9];
    const float* gk   = (const float*)d_in[10];
    const float* fcos = (const float*)d_in[11];
    const float* fsin = (const float*)d_in[12];

    float *Qp, *Kp, *Vp, *Ap;
    cudaGetSymbolAddress((void**)&Qp, g_Q);
    cudaGetSymbolAddress((void**)&Kp, g_K);
    cudaGetSymbolAddress((void**)&Vp, g_V);
    cudaGetSymbolAddress((void**)&Ap, g_A);

    cudaFuncSetAttribute(attn_mma_kernel, cudaFuncAttributeMaxDynamicSharedMemorySize,
                         ATT_SMEM_BYTES);

    dim3 gemm_grid(D_MODEL/128, L_TOK/128);   // (12, 32)

    mma_gemm_kernel<0><<<gemm_grid, 256>>>(x, wq, bq, Qp, L_TOK, D_MODEL, D_MODEL);
    mma_gemm_kernel<0><<<gemm_grid, 256>>>(x, wk, bk, Kp, L_TOK, D_MODEL, D_MODEL);
    mma_gemm_kernel<1><<<gemm_grid, 256>>>(x, wv, bv, Vp, L_TOK, D_MODEL, D_MODEL);

    norm_rope_kernel<<<dim3(L_TOK, 2), 256>>>(gq, gk, fcos, fsin);

    attn_mma_kernel<<<dim3(L_TOK/128, N_HEADS), 256, ATT_SMEM_BYTES>>>(Qp, Kp, Vp, Ap);

    mma_gemm_kernel<0><<<gemm_grid, 256>>>(Ap, wo, bo, (float*)d_out,
                                           L_TOK, D_MODEL, D_MODEL);
}

// round 12
// speedup vs baseline: 3.2028x; 1.0168x over previous
#include <cuda_runtime.h>
#include <math.h>
#include <stdint.h>

#define L_TOK   4096
#define D_MODEL 1536
#define N_HEADS 12
#define H_DIM   128
#define QK_SCALE 0.08838834764831845f  /* 1/sqrt(128) */

// -------- scratch (allocation-free: __device__ globals) --------
__device__ float g_Q[L_TOK * D_MODEL];
__device__ float g_K[L_TOK * D_MODEL];
__device__ float g_V[L_TOK * D_MODEL];   // holds V^T: [D_MODEL][L_TOK]
__device__ float g_A[L_TOK * D_MODEL];   // attention out (tf32-rounded)
__device__ float g_X[L_TOK * D_MODEL];   // x pre-converted to tf32
__device__ float g_W[4 * D_MODEL * D_MODEL]; // wq,wk,wv,wo pre-converted

// =================================================================
// helpers
// =================================================================
__device__ __forceinline__ uint32_t tf32r(float x) {
    uint32_t r;
    asm("cvt.rna.tf32.f32 %0, %1;" : "=r"(r) : "f"(x));
    return r;
}

__device__ __forceinline__ uint32_t smem_u32(const void* p) {
    uint32_t a;
    asm("{ .reg .u64 t; cvta.to.shared.u64 t, %1; cvt.u32.u64 %0, t; }"
        : "=r"(a) : "l"(p));
    return a;
}

__device__ __forceinline__ void cp_async16(uint32_t dst, const float* src) {
    asm volatile("cp.async.cg.shared.global [%0], [%1], 16;"
                 :: "r"(dst), "l"(src) : "memory");
}
#define CP_COMMIT() asm volatile("cp.async.commit_group;" ::: "memory")
#define CP_WAIT1()  asm volatile("cp.async.wait_group 1;" ::: "memory")

// D(m16n8) += A(m16k8,row) * B(k8n8,col)   tf32 inputs, f32 accum
__device__ __forceinline__ void mma_tf32(float* d,
                                         uint32_t a0, uint32_t a1,
                                         uint32_t a2, uint32_t a3,
                                         uint32_t b0, uint32_t b1) {
    asm volatile(
        "mma.sync.aligned.m16n8k8.row.col.f32.tf32.tf32.f32 "
        "{%0,%1,%2,%3}, {%4,%5,%6,%7}, {%8,%9}, {%0,%1,%2,%3};"
        : "+f"(d[0]), "+f"(d[1]), "+f"(d[2]), "+f"(d[3])
        : "r"(a0), "r"(a1), "r"(a2), "r"(a3), "r"(b0), "r"(b1));
}

// =================================================================
// tf32 round pre-pass: dst[i] = round_rna_tf32(src[i]) as fp32 bits
// grid*256*4 must equal element count.
// =================================================================
__global__ __launch_bounds__(256) void cvt_tf32_kernel(
    const float* __restrict__ s, float* __restrict__ d)
{
    size_t i = ((size_t)blockIdx.x * 256 + threadIdx.x) * 4;
    float4 v = *(const float4*)(s + i);
    uint4 u = make_uint4(tf32r(v.x), tf32r(v.y), tf32r(v.z), tf32r(v.w));
    *(uint4*)(d + i) = u;
}

// =================================================================
// tf32 mma.sync GEMM with 3-stage cp.async pipeline.
// Inputs MUST already be tf32-rounded fp32 (no cvt in loop).
// C[M,N] = A[M,K] @ W[N,K]^T + bias. CTA 128x128, 8 warps (4Mx2N),
// warp tile 32x64, BK=32. TRANSPOSED=1 writes C^T [N][M].
// Dynamic smem = 3 stages * (128+128)*36 words = 108 KB.
// =================================================================
#define SROW 36
#define NSTAGE 3
#define STAGE_WORDS (2 * 128 * SROW)
#define GEMM_SMEM_BYTES (NSTAGE * STAGE_WORDS * 4)

template <int TRANSPOSED>
__global__ __launch_bounds__(256) void mma_gemm_cp(
    const float* __restrict__ A, const float* __restrict__ W,
    const float* __restrict__ bias, float* __restrict__ C,
    int M, int N, int K)
{
    extern __shared__ __align__(16) uint32_t smw[];

    const int tid    = threadIdx.x;
    const int wid    = tid >> 5;
    const int lane   = tid & 31;
    const int warp_m = wid & 3;
    const int warp_n = wid >> 2;
    const int bm     = blockIdx.y * 128;
    const int bn     = blockIdx.x * 128;
    const int g      = lane >> 2;
    const int q      = lane & 3;

    float acc[2][8][4];
#pragma unroll
    for (int mt = 0; mt < 2; mt++)
#pragma unroll
        for (int nt = 0; nt < 8; nt++)
#pragma unroll
            for (int c = 0; c < 4; c++) acc[mt][nt][c] = 0.f;

    // loader mapping: 2 threads per row, 16 consecutive k each (4x 16B)
    const int lrow  = tid >> 1;
    const int lhalf = (tid & 1) * 16;
    const float* Ap = A + (size_t)(bm + lrow) * K + lhalf;
    const float* Wp = W + (size_t)(bn + lrow) * K + lhalf;
    const uint32_t sbase   = smem_u32(smw);
    const uint32_t sOffB   = ((uint32_t)lrow * SROW + (uint32_t)lhalf) * 4u;

    const int nIter = K / 32;   // 48

    auto issue = [&](int it) {
        const int s = it % NSTAGE;
        const uint32_t aDst = sbase + (uint32_t)s * (STAGE_WORDS * 4u) + sOffB;
        const uint32_t wDst = aDst + 128u * SROW * 4u;
        const float* ag = Ap + it * 32;
        const float* wg = Wp + it * 32;
#pragma unroll
        for (int i = 0; i < 4; i++) {
            cp_async16(aDst + i * 16u, ag + i * 4);
            cp_async16(wDst + i * 16u, wg + i * 4);
        }
    };

    issue(0); CP_COMMIT();
    issue(1); CP_COMMIT();

    const int aBaseM0 = warp_m * 32;
    const int bBaseN  = warp_n * 64;

    for (int it = 0; it < nIter; it++) {
        CP_WAIT1();           // stage `it` landed (stage it+1 may be in flight)
        __syncthreads();      // all warps past iter it-1 MMAs; copies visible
        if (it + 2 < nIter) issue(it + 2);   // overwrites buf consumed at it-1
        CP_COMMIT();

        const uint32_t* As = smw + (it % NSTAGE) * STAGE_WORDS;
        const uint32_t* Ws = As + 128 * SROW;

#pragma unroll
        for (int ks = 0; ks < 4; ks++) {
            const int kk = ks * 8;
            uint32_t a[2][4];
#pragma unroll
            for (int mt = 0; mt < 2; mt++) {
                const int r = aBaseM0 + mt * 16;
                a[mt][0] = As[(r + g)     * SROW + kk + q];
                a[mt][1] = As[(r + g + 8) * SROW + kk + q];
                a[mt][2] = As[(r + g)     * SROW + kk + q + 4];
                a[mt][3] = As[(r + g + 8) * SROW + kk + q + 4];
            }
#pragma unroll
            for (int nt = 0; nt < 8; nt++) {
                const int c = bBaseN + nt * 8;
                uint32_t b0 = Ws[(c + g) * SROW + kk + q];
                uint32_t b1 = Ws[(c + g) * SROW + kk + q + 4];
                mma_tf32(acc[0][nt], a[0][0], a[0][1], a[0][2], a[0][3], b0, b1);
                mma_tf32(acc[1][nt], a[1][0], a[1][1], a[1][2], a[1][3], b0, b1);
            }
        }
    }

    // epilogue
#pragma unroll
    for (int mt = 0; mt < 2; mt++) {
        const int row0 = bm + aBaseM0 + mt * 16 + g;
#pragma unroll
        for (int nt = 0; nt < 8; nt++) {
            const int col = bn + bBaseN + nt * 8 + q * 2;
            const float2 bb = *(const float2*)&bias[col];
            if (TRANSPOSED) {
                C[(size_t)col       * M + row0]     = acc[mt][nt][0] + bb.x;
                C[(size_t)(col + 1) * M + row0]     = acc[mt][nt][1] + bb.y;
                C[(size_t)col       * M + row0 + 8] = acc[mt][nt][2] + bb.x;
                C[(size_t)(col + 1) * M + row0 + 8] = acc[mt][nt][3] + bb.y;
            } else {
                float2 r0, r1;
                r0.x = acc[mt][nt][0] + bb.x;
                r0.y = acc[mt][nt][1] + bb.y;
                r1.x = acc[mt][nt][2] + bb.x;
                r1.y = acc[mt][nt][3] + bb.y;
                *(float2*)&C[(size_t)row0 * N + col]       = r0;
                *(float2*)&C[(size_t)(row0 + 8) * N + col] = r1;
            }
        }
    }
}

// =================================================================
// Fused full-D RMSNorm + 3-axis RoPE, in-place on g_Q / g_K.
// =================================================================
__global__ __launch_bounds__(256) void norm_rope_kernel(
    const float* __restrict__ gq, const float* __restrict__ gk,
    const float* __restrict__ fcos, const float* __restrict__ fsin)
{
    const int l = blockIdx.x;
    float* row = (blockIdx.y == 0 ? g_Q : g_K) + (size_t)l * D_MODEL;
    const float* g = (blockIdx.y == 0) ? gq : gk;
    const int tid = threadIdx.x;

    float2 v[3];
    float ss = 0.f;
#pragma unroll
    for (int t = 0; t < 3; t++) {
        int p = tid + t * 256;
        v[t] = *(const float2*)&row[2*p];
        ss += v[t].x*v[t].x + v[t].y*v[t].y;
    }
#pragma unroll
    for (int s = 16; s; s >>= 1) ss += __shfl_xor_sync(0xffffffffu, ss, s);

    __shared__ float warp_ss[8];
    __shared__ float inv_s;
    if ((tid & 31) == 0) warp_ss[tid >> 5] = ss;
    __syncthreads();
    if (tid == 0) {
        float tot = 0.f;
#pragma unroll
        for (int i = 0; i < 8; i++) tot += warp_ss[i];
        inv_s = rsqrtf(tot / (float)D_MODEL + 1e-6f);
    }
    __syncthreads();
    const float inv = inv_s;

    const int fi = l >> 10;
    const int hi = (l >> 5) & 31;
    const int wi = l & 31;

#pragma unroll
    for (int t = 0; t < 3; t++) {
        int p = tid + t * 256;
        int c = p & 63;
        int rowi = (c < 22) ? fi : ((c < 43) ? hi : wi);
        float cv = fcos[rowi * 64 + c];
        float sv = fsin[rowi * 64 + c];
        float xr = v[t].x * inv * g[2*p];
        float xi = v[t].y * inv * g[2*p+1];
        float2 o;
        o.x = xr * cv - xi * sv;
        o.y = xr * sv + xi * cv;
        *(float2*)&row[2*p] = o;
    }
}

// =================================================================
// tf32 mma.sync flash attention (validated R10 design).
// CTA = 128 Q-rows x 1 head, 8 warps, K-tile 64. Epilogue now writes
// tf32-rounded values so the O-projection GEMM needs no cvt.
// =================================================================
#define AKS_OFF 0
#define AVT_OFF (64*132)
#define APS_OFF (64*132 + 128*68)
#define ATT_SMEM_WORDS (64*132 + 2*128*68)
#define ATT_SMEM_BYTES (ATT_SMEM_WORDS * 4)

__global__ __launch_bounds__(256) void attn_mma_kernel(
    const float* __restrict__ Q, const float* __restrict__ K,
    const float* __restrict__ Vt, float* __restrict__ O)
{
    extern __shared__ __align__(16) uint32_t smw[];
    const int tid  = threadIdx.x;
    const int lane = tid & 31;
    const int wid  = tid >> 5;
    const int g    = lane >> 2;
    const int q    = lane & 3;
    const int head = blockIdx.y;
    const int q0   = blockIdx.x * 128;
    const int hoff = head * H_DIM;
    const int mrow = wid * 16;

    // ---- stage Q (pre-scaled, tf32) then lift fragments to regs ----
#pragma unroll
    for (int it = 0; it < 16; it++) {
        int ci = it * 256 + tid;
        int r  = ci >> 5, cq = ci & 31;
        float4 v = *(const float4*)&Q[(size_t)(q0 + r) * D_MODEL + hoff + cq * 4];
        uint4 u = make_uint4(tf32r(v.x * QK_SCALE), tf32r(v.y * QK_SCALE),
                             tf32r(v.z * QK_SCALE), tf32r(v.w * QK_SCALE));
        *(uint4*)&smw[r * 132 + cq * 4] = u;
    }
    __syncthreads();
    uint32_t qa[16][4];
#pragma unroll
    for (int ks = 0; ks < 16; ks++) {
        const int kk = ks * 8;
        qa[ks][0] = smw[(mrow + g)     * 132 + kk + q];
        qa[ks][1] = smw[(mrow + g + 8) * 132 + kk + q];
        qa[ks][2] = smw[(mrow + g)     * 132 + kk + q + 4];
        qa[ks][3] = smw[(mrow + g + 8) * 132 + kk + q + 4];
    }

    uint32_t* Ks  = smw + AKS_OFF;
    uint32_t* Vts = smw + AVT_OFF;
    uint32_t* Ps  = smw + APS_OFF;

    float m0 = -1e30f, m1 = -1e30f, l0 = 0.f, l1 = 0.f;
    float Oa[16][4];
#pragma unroll
    for (int nt = 0; nt < 16; nt++)
#pragma unroll
        for (int c = 0; c < 4; c++) Oa[nt][c] = 0.f;

    for (int kb = 0; kb < L_TOK / 64; kb++) {
        const int k0 = kb * 64;
        __syncthreads();
#pragma unroll
        for (int it = 0; it < 8; it++) {
            int ci = it * 256 + tid;
            int r  = ci >> 5, cq = ci & 31;
            float4 v = *(const float4*)&K[(size_t)(k0 + r) * D_MODEL + hoff + cq * 4];
            *(uint4*)&Ks[r * 132 + cq * 4] =
                make_uint4(tf32r(v.x), tf32r(v.y), tf32r(v.z), tf32r(v.w));
        }
#pragma unroll
        for (int it = 0; it < 8; it++) {
            int ci = it * 256 + tid;
            int r  = ci >> 4, cf = ci & 15;
            float4 v = *(const float4*)&Vt[(size_t)(hoff + r) * L_TOK + k0 + cf * 4];
            *(uint4*)&Vts[r * 68 + cf * 4] =
                make_uint4(tf32r(v.x), tf32r(v.y), tf32r(v.z), tf32r(v.w));
        }
        __syncthreads();

        float s[8][4];
#pragma unroll
        for (int nt = 0; nt < 8; nt++)
#pragma unroll
            for (int c = 0; c < 4; c++) s[nt][c] = 0.f;

#pragma unroll
        for (int ks = 0; ks < 16; ks++) {
            const int kk = ks * 8;
#pragma unroll
            for (int nt = 0; nt < 8; nt++) {
                uint32_t b0 = Ks[(nt * 8 + g) * 132 + kk + q];
                uint32_t b1 = Ks[(nt * 8 + g) * 132 + kk + q + 4];
                mma_tf32(s[nt], qa[ks][0], qa[ks][1], qa[ks][2], qa[ks][3], b0, b1);
            }
        }

        float rm0 = -1e30f, rm1 = -1e30f;
#pragma unroll
        for (int nt = 0; nt < 8; nt++) {
            rm0 = fmaxf(rm0, fmaxf(s[nt][0], s[nt][1]));
            rm1 = fmaxf(rm1, fmaxf(s[nt][2], s[nt][3]));
        }
        rm0 = fmaxf(rm0, __shfl_xor_sync(0xffffffffu, rm0, 1));
        rm0 = fmaxf(rm0, __shfl_xor_sync(0xffffffffu, rm0, 2));
        rm1 = fmaxf(rm1, __shfl_xor_sync(0xffffffffu, rm1, 1));
        rm1 = fmaxf(rm1, __shfl_xor_sync(0xffffffffu, rm1, 2));

        const float mn0 = fmaxf(m0, rm0);
        const float mn1 = fmaxf(m1, rm1);
        const float cr0 = __expf(m0 - mn0);
        const float cr1 = __expf(m1 - mn1);
        m0 = mn0; m1 = mn1;

        float rs0 = 0.f, rs1 = 0.f;
#pragma unroll
        for (int nt = 0; nt < 8; nt++) {
            s[nt][0] = __expf(s[nt][0] - mn0);
            s[nt][1] = __expf(s[nt][1] - mn0);
            s[nt][2] = __expf(s[nt][2] - mn1);
            s[nt][3] = __expf(s[nt][3] - mn1);
            rs0 += s[nt][0] + s[nt][1];
            rs1 += s[nt][2] + s[nt][3];
        }
        rs0 += __shfl_xor_sync(0xffffffffu, rs0, 1);
        rs0 += __shfl_xor_sync(0xffffffffu, rs0, 2);
        rs1 += __shfl_xor_sync(0xffffffffu, rs1, 1);
        rs1 += __shfl_xor_sync(0xffffffffu, rs1, 2);
        l0 = l0 * cr0 + rs0;
        l1 = l1 * cr1 + rs1;

#pragma unroll
        for (int nt = 0; nt < 16; nt++) {
            Oa[nt][0] *= cr0; Oa[nt][1] *= cr0;
            Oa[nt][2] *= cr1; Oa[nt][3] *= cr1;
        }

#pragma unroll
        for (int nt = 0; nt < 8; nt++) {
            *(uint2*)&Ps[(mrow + g)     * 68 + nt * 8 + 2 * q] =
                make_uint2(tf32r(s[nt][0]), tf32r(s[nt][1]));
            *(uint2*)&Ps[(mrow + g + 8) * 68 + nt * 8 + 2 * q] =
                make_uint2(tf32r(s[nt][2]), tf32r(s[nt][3]));
        }
        __syncwarp();

#pragma unroll
        for (int ks = 0; ks < 8; ks++) {
            const int kk = ks * 8;
            uint32_t pa0 = Ps[(mrow + g)     * 68 + kk + q];
            uint32_t pa1 = Ps[(mrow + g + 8) * 68 + kk + q];
            uint32_t pa2 = Ps[(mrow + g)     * 68 + kk + q + 4];
            uint32_t pa3 = Ps[(mrow + g + 8) * 68 + kk + q + 4];
#pragma unroll
            for (int nt = 0; nt < 16; nt++) {
                uint32_t b0 = Vts[(nt * 8 + g) * 68 + kk + q];
                uint32_t b1 = Vts[(nt * 8 + g) * 68 + kk + q + 4];
                mma_tf32(Oa[nt], pa0, pa1, pa2, pa3, b0, b1);
            }
        }
        __syncwarp();
    }

    // ---- epilogue: write tf32-rounded (exact for downstream O-GEMM) ----
    const float i0 = 1.f / l0;
    const float i1 = 1.f / l1;
    const int r0 = q0 + mrow + g;
#pragma unroll
    for (int nt = 0; nt < 16; nt++) {
        const int col = hoff + nt * 8 + 2 * q;
        uint2 w0, w1;
        w0.x = tf32r(Oa[nt][0] * i0); w0.y = tf32r(Oa[nt][1] * i0);
        w1.x = tf32r(Oa[nt][2] * i1); w1.y = tf32r(Oa[nt][3] * i1);
        *(uint2*)&O[(size_t)r0 * D_MODEL + col]       = w0;
        *(uint2*)&O[(size_t)(r0 + 8) * D_MODEL + col] = w1;
    }
}

// =================================================================
// launch
// =================================================================
extern "C" void kernel_launch(void* const* d_in, const int* in_sizes, int n_in,
                              void* d_out, int out_size)
{
    (void)in_sizes; (void)n_in; (void)out_size;
    const float* x    = (const float*)d_in[0];
    const float* wq   = (const float*)d_in[1];
    const float* wk   = (const float*)d_in[2];
    const float* wv   = (const float*)d_in[3];
    const float* wo   = (const float*)d_in[4];
    const float* bq   = (const float*)d_in[5];
    const float* bk   = (const float*)d_in[6];
    const float* bv   = (const float*)d_in[7];
    const float* bo   = (const float*)d_in[8];
    const float* gq   = (const float*)d_in[9];
    const float* gk   = (const float*)d_in[10];
    const float* fcos = (const float*)d_in[11];
    const float* fsin = (const float*)d_in[12];

    float *Qp, *Kp, *Vp, *Ap, *Xp, *Wp;
    cudaGetSymbolAddress((void**)&Qp, g_Q);
    cudaGetSymbolAddress((void**)&Kp, g_K);
    cudaGetSymbolAddress((void**)&Vp, g_V);
    cudaGetSymbolAddress((void**)&Ap, g_A);
    cudaGetSymbolAddress((void**)&Xp, g_X);
    cudaGetSymbolAddress((void**)&Wp, g_W);

    float* Wqc = Wp;
    float* Wkc = Wp + (size_t)D_MODEL * D_MODEL;
    float* Wvc = Wp + 2 * (size_t)D_MODEL * D_MODEL;
    float* Woc = Wp + 3 * (size_t)D_MODEL * D_MODEL;

    cudaFuncSetAttribute(mma_gemm_cp<0>, cudaFuncAttributeMaxDynamicSharedMemorySize,
                         GEMM_SMEM_BYTES);
    cudaFuncSetAttribute(mma_gemm_cp<1>, cudaFuncAttributeMaxDynamicSharedMemorySize,
                         GEMM_SMEM_BYTES);
    cudaFuncSetAttribute(attn_mma_kernel, cudaFuncAttributeMaxDynamicSharedMemorySize,
                         ATT_SMEM_BYTES);

    // pre-convert GEMM inputs to tf32 (rna) once
    const int xBlocks = (L_TOK * D_MODEL) / 1024;        // 6144
    const int wBlocks = (D_MODEL * D_MODEL) / 1024;      // 2304
    cvt_tf32_kernel<<<xBlocks, 256>>>(x, Xp);
    cvt_tf32_kernel<<<wBlocks, 256>>>(wq, Wqc);
    cvt_tf32_kernel<<<wBlocks, 256>>>(wk, Wkc);
    cvt_tf32_kernel<<<wBlocks, 256>>>(wv, Wvc);
    cvt_tf32_kernel<<<wBlocks, 256>>>(wo, Woc);

    dim3 gemm_grid(D_MODEL/128, L_TOK/128);   // (12, 32)

    mma_gemm_cp<0><<<gemm_grid, 256, GEMM_SMEM_BYTES>>>(Xp, Wqc, bq, Qp,
                                                        L_TOK, D_MODEL, D_MODEL);
    mma_gemm_cp<0><<<gemm_grid, 256, GEMM_SMEM_BYTES>>>(Xp, Wkc, bk, Kp,
                                                        L_TOK, D_MODEL, D_MODEL);
    mma_gemm_cp<1><<<gemm_grid, 256, GEMM_SMEM_BYTES>>>(Xp, Wvc, bv, Vp,
                                                        L_TOK, D_MODEL, D_MODEL);

    norm_rope_kernel<<<dim3(L_TOK, 2), 256>>>(gq, gk, fcos, fsin);

    attn_mma_kernel<<<dim3(L_TOK/128, N_HEADS), 256, ATT_SMEM_BYTES>>>(Qp, Kp, Vp, Ap);

    mma_gemm_cp<0><<<gemm_grid, 256, GEMM_SMEM_BYTES>>>(Ap, Woc, bo, (float*)d_out,
                                                        L_TOK, D_MODEL, D_MODEL);
}